// round 14
// baseline (speedup 1.0000x reference)
#include <cuda_runtime.h>
#include <cuda_fp16.h>
#include <cstdint>
#include <math.h>

#define BATCH 4
#define CDIM  64
#define NPIX  6400
#define QT    64
#define NSUB  100   // 64-col subtiles

__device__ float  g_q[BATCH * NPIX * CDIM];   // projected q, [b][n][c], scaled by 0.125*log2e
__device__ __half g_k[BATCH * CDIM * NPIX];   // fp16 keys,   [b][c][m]
__device__ __half g_v[BATCH * CDIM * NPIX];   // fp16 values, [b][c][m]

// ---------------- helpers ----------------
__device__ __forceinline__ uint32_t smem_u32(const void* p) {
    uint32_t a;
    asm("{ .reg .u64 t; cvta.to.shared.u64 t, %1; cvt.u32.u64 %0, t; }" : "=r"(a) : "l"(p));
    return a;
}
__device__ __forceinline__ uint32_t pkhf(float hi, float lo) {
    uint32_t d; asm("cvt.rn.f16x2.f32 %0, %1, %2;" : "=r"(d) : "f"(hi), "f"(lo));
    return d;
}
__device__ __forceinline__ uint32_t ex2h2(uint32_t x) {
    uint32_t d; asm("ex2.approx.f16x2 %0, %1;" : "=r"(d) : "r"(x));
    return d;
}
__device__ __forceinline__ void cp16(uint32_t dst, const void* src) {
    asm volatile("cp.async.cg.shared.global [%0], [%1], 16;" :: "r"(dst), "l"(src) : "memory");
}
#define CP_COMMIT() asm volatile("cp.async.commit_group;" ::: "memory")
#define CP_WAIT0()  asm volatile("cp.async.wait_group 0;"  ::: "memory")
#define CP_WAIT1()  asm volatile("cp.async.wait_group 1;"  ::: "memory")

__device__ __forceinline__ void ldsm4(uint32_t* r, uint32_t a) {
    asm volatile("ldmatrix.sync.aligned.m8n8.x4.shared.b16 {%0,%1,%2,%3}, [%4];"
                 : "=r"(r[0]), "=r"(r[1]), "=r"(r[2]), "=r"(r[3]) : "r"(a));
}
__device__ __forceinline__ void ldsm4t(uint32_t* r, uint32_t a) {
    asm volatile("ldmatrix.sync.aligned.m8n8.x4.trans.shared.b16 {%0,%1,%2,%3}, [%4];"
                 : "=r"(r[0]), "=r"(r[1]), "=r"(r[2]), "=r"(r[3]) : "r"(a));
}
__device__ __forceinline__ void mma16(float* c, const uint32_t* a, uint32_t b0, uint32_t b1) {
    asm volatile("mma.sync.aligned.m16n8k16.row.col.f32.f16.f16.f32 "
                 "{%0,%1,%2,%3},{%4,%5,%6,%7},{%8,%9},{%0,%1,%2,%3};"
                 : "+f"(c[0]), "+f"(c[1]), "+f"(c[2]), "+f"(c[3])
                 : "r"(a[0]), "r"(a[1]), "r"(a[2]), "r"(a[3]), "r"(b0), "r"(b1));
}

// smem: 4-deep ring of 64-col subtiles, K[4][64][72] + V[4][64][72] halves
#define TILE_B  9216u
#define SMEM_BYTES (8u * TILE_B)   // 73728

// ---------------- Kernel 0: fp32 -> fp16 conversion, 4x float4 per thread ------
__global__ void cvt_kernel(const float* __restrict__ keys, const float* __restrict__ values)
{
    const int base = blockIdx.x * 1024 + threadIdx.x;
#pragma unroll
    for (int j = 0; j < 4; j++) {
        const int idx = base + j * 256;
        const float4 kv = ((const float4*)keys)[idx];
        const float4 vv = ((const float4*)values)[idx];
        uint2 ko, vo;
        ko.x = pkhf(kv.y, kv.x); ko.y = pkhf(kv.w, kv.z);
        vo.x = pkhf(vv.y, vv.x); vo.y = pkhf(vv.w, vv.z);
        ((uint2*)g_k)[idx] = ko;
        ((uint2*)g_v)[idx] = vo;
    }
}

// ---------------- Kernel 1: q projection (scale folds in log2e) ----------------
__global__ void qproj_kernel(const float* __restrict__ query,
                             const float* __restrict__ Wq,
                             const float* __restrict__ bq)
{
    __shared__ float wt[CDIM * CDIM];
    __shared__ float xs[CDIM * 64];
    const int b  = blockIdx.y;
    const int n0 = blockIdx.x * 64;
    const int tid = threadIdx.x;

    for (int e = tid; e < CDIM * CDIM; e += 256) {
        int c = e >> 6, d = e & 63;
        wt[d * CDIM + c] = Wq[e];
    }
    const float* qbase = query + (size_t)b * CDIM * NPIX + n0;
    for (int e = tid; e < CDIM * 64; e += 256) {
        int d = e >> 6, n = e & 63;
        xs[d * 64 + n] = qbase[(size_t)d * NPIX + n];
    }
    __syncthreads();

    const int ty = tid >> 4, tx = tid & 15;
    float acc[4][4] = {};
#pragma unroll 8
    for (int d = 0; d < CDIM; d++) {
        float4 xv = *(const float4*)&xs[d * 64 + 4 * ty];
        float4 wv = *(const float4*)&wt[d * CDIM + 4 * tx];
        float xa[4] = {xv.x, xv.y, xv.z, xv.w};
        float wa[4] = {wv.x, wv.y, wv.z, wv.w};
#pragma unroll
        for (int i = 0; i < 4; i++)
#pragma unroll
            for (int j = 0; j < 4; j++)
                acc[i][j] += xa[i] * wa[j];
    }
    const float scale = 0.125f * 1.4426950408889634f;
    float bj[4];
#pragma unroll
    for (int j = 0; j < 4; j++) bj[j] = bq[4 * tx + j];
#pragma unroll
    for (int i = 0; i < 4; i++) {
        int n = n0 + 4 * ty + i;
        float4 o;
        o.x = (acc[i][0] + bj[0]) * scale;
        o.y = (acc[i][1] + bj[1]) * scale;
        o.z = (acc[i][2] + bj[2]) * scale;
        o.w = (acc[i][3] + bj[3]) * scale;
        *(float4*)&g_q[((size_t)b * NPIX + n) * CDIM + 4 * tx] = o;
    }
}

// ---------------- KV fp16 subtile loader (64 cols) via cp.async, 128 threads ---
__device__ __forceinline__ void load_kv(uint32_t ksb, uint32_t vsb,
                                        const __half* kb, const __half* vb,
                                        int m0, int tid)
{
#pragma unroll
    for (int i = 0; i < 4; i++) {
        int idx = tid + (i << 7);          // 0..511
        int c = idx >> 3, m = (idx & 7) << 3;
        uint32_t soff = (uint32_t)(c * 72 + m) * 2u;
        cp16(ksb + soff, kb + (size_t)c * NPIX + m0 + m);
        cp16(vsb + soff, vb + (size_t)c * NPIX + m0 + m);
    }
    CP_COMMIT();
}

// ---------------- Pipelined subtile step: GEMM1(j) + deferred GEMM2(j-1) -------
// Warp = 16 rows x 64 cols. s (8 nf-frags), p16 = prev P A-frags (4 kt).
template<bool DO2>
__device__ __forceinline__ void subtile_step(
    uint32_t kbb, uint32_t vbp, uint32_t kaddr0, uint32_t vaddr0,
    const uint32_t (&qa)[4][4], uint32_t (&p16)[4][4],
    float (&o)[8][4], float (&lacc)[4])
{
    const uint32_t ONES = 0x3C003C00u;
    float s[8][4] = {};
#pragma unroll
    for (int ks = 0; ks < 4; ks++) {
        // GEMM1 quarter: k-chunk ks, all 64 n-cols
        uint32_t r0f[4], r1f[4];
        ldsm4t(r0f, kbb + kaddr0 + (uint32_t)(ks * 16 * 72) * 2u);
        ldsm4t(r1f, kbb + kaddr0 + (uint32_t)(ks * 16 * 72 + 16) * 2u);
        mma16(s[0], qa[ks], r0f[0], r0f[1]);
        mma16(s[1], qa[ks], r0f[2], r0f[3]);
        mma16(s[2], qa[ks], r1f[0], r1f[1]);
        mma16(s[3], qa[ks], r1f[2], r1f[3]);
        if (DO2) {   // GEMM2 quarter of previous subtile, kt = ks
            uint32_t v[4];
            ldsm4(v, vbp + vaddr0 + (uint32_t)(0 * 16 * 72 + ks * 16) * 2u);
            mma16(o[0], p16[ks], v[0], v[1]);
            mma16(o[1], p16[ks], v[2], v[3]);
            ldsm4(v, vbp + vaddr0 + (uint32_t)(1 * 16 * 72 + ks * 16) * 2u);
            mma16(o[2], p16[ks], v[0], v[1]);
            mma16(o[3], p16[ks], v[2], v[3]);
        }
        ldsm4t(r0f, kbb + kaddr0 + (uint32_t)(ks * 16 * 72 + 32) * 2u);
        ldsm4t(r1f, kbb + kaddr0 + (uint32_t)(ks * 16 * 72 + 48) * 2u);
        mma16(s[4], qa[ks], r0f[0], r0f[1]);
        mma16(s[5], qa[ks], r0f[2], r0f[3]);
        mma16(s[6], qa[ks], r1f[0], r1f[1]);
        mma16(s[7], qa[ks], r1f[2], r1f[3]);
        if (DO2) {
            uint32_t v[4];
            ldsm4(v, vbp + vaddr0 + (uint32_t)(2 * 16 * 72 + ks * 16) * 2u);
            mma16(o[4], p16[ks], v[0], v[1]);
            mma16(o[5], p16[ks], v[2], v[3]);
            ldsm4(v, vbp + vaddr0 + (uint32_t)(3 * 16 * 72 + ks * 16) * 2u);
            mma16(o[6], p16[ks], v[0], v[1]);
            mma16(o[7], p16[ks], v[2], v[3]);
            mma16(lacc, p16[ks], ONES, ONES);
        }
    }
    // softmax (no max): pack + packed exp2 -> this subtile's P A-frags
#pragma unroll
    for (int kt = 0; kt < 4; kt++) {
        p16[kt][0] = ex2h2(pkhf(s[2 * kt][1],     s[2 * kt][0]));
        p16[kt][1] = ex2h2(pkhf(s[2 * kt][3],     s[2 * kt][2]));
        p16[kt][2] = ex2h2(pkhf(s[2 * kt + 1][1], s[2 * kt + 1][0]));
        p16[kt][3] = ex2h2(pkhf(s[2 * kt + 1][3], s[2 * kt + 1][2]));
    }
}

// ---------------- Kernel 2: fp16 mma flash attention, cross-subtile pipeline ---
__global__ void __launch_bounds__(128, 3)
attn_kernel(float* __restrict__ out)
{
    extern __shared__ uint32_t smu[];
    const uint32_t sbase = smem_u32(smu);
    const int tid  = threadIdx.x;
    const int lane = tid & 31, warp = tid >> 5;
    const int g = lane >> 2, t = lane & 3;
    const int b  = blockIdx.y;
    const int r0 = blockIdx.x * QT;

    const uint32_t KS0 = sbase;
    const uint32_t VS0 = sbase + 4u * TILE_B;
    const uint32_t ONES = 0x3C003C00u;

    // Q A-fragments (fp16): warp owns rows r0 + warp*16 .. +15
    uint32_t qa[4][4];
    {
        const float* qp = g_q + ((size_t)b * NPIX + r0 + warp * 16) * CDIM;
#pragma unroll
        for (int ks = 0; ks < 4; ks++) {
            const int c = ks * 16 + 2 * t;
            qa[ks][0] = pkhf(qp[(size_t)g * CDIM + c + 1],        qp[(size_t)g * CDIM + c]);
            qa[ks][1] = pkhf(qp[(size_t)(g + 8) * CDIM + c + 1],  qp[(size_t)(g + 8) * CDIM + c]);
            qa[ks][2] = pkhf(qp[(size_t)g * CDIM + c + 9],        qp[(size_t)g * CDIM + c + 8]);
            qa[ks][3] = pkhf(qp[(size_t)(g + 8) * CDIM + c + 9],  qp[(size_t)(g + 8) * CDIM + c + 8]);
        }
    }

    const __half* kb = g_k + (size_t)b * CDIM * NPIX;
    const __half* vb = g_v + (size_t)b * CDIM * NPIX;
    load_kv(KS0, VS0, kb, vb, 0, tid);                       // L0
    load_kv(KS0 + TILE_B, VS0 + TILE_B, kb, vb, 64, tid);    // L1

    // LDSM lane-address bases (halves -> bytes x2)
    const uint32_t kaddr0 = ((uint32_t)((lane & 15) * 72) + (uint32_t)((lane >> 4) << 3)) * 2u;
    const uint32_t vaddr0 = ((uint32_t)(((lane & 7) + ((lane >> 4) << 3)) * 72)
                             + (uint32_t)(((lane >> 3) & 1) << 3)) * 2u;

    float o[8][4] = {};
    float lacc[4] = {};
    uint32_t p16[4][4];

    for (int j = 0; j < NSUB; j++) {
        if (j < NSUB - 2) CP_WAIT1(); else CP_WAIT0();   // L_j complete
        __syncthreads();
        if (j + 2 < NSUB)
            load_kv(KS0 + (uint32_t)((j + 2) & 3) * TILE_B,
                    VS0 + (uint32_t)((j + 2) & 3) * TILE_B, kb, vb, (j + 2) * 64, tid);
        const uint32_t kbb = KS0 + (uint32_t)(j & 3) * TILE_B;
        const uint32_t vbp = VS0 + (uint32_t)((j - 1) & 3) * TILE_B;
        if (j == 0)
            subtile_step<false>(kbb, 0u, kaddr0, vaddr0, qa, p16, o, lacc);
        else
            subtile_step<true>(kbb, vbp, kaddr0, vaddr0, qa, p16, o, lacc);
    }
    // drain GEMM2 of last subtile
    {
        const uint32_t vbp = VS0 + (uint32_t)((NSUB - 1) & 3) * TILE_B;
#pragma unroll
        for (int kt = 0; kt < 4; kt++) {
#pragma unroll
            for (int ct = 0; ct < 4; ct++) {
                uint32_t v[4];
                ldsm4(v, vbp + vaddr0 + (uint32_t)(ct * 16 * 72 + kt * 16) * 2u);
                mma16(o[2 * ct],     p16[kt], v[0], v[1]);
                mma16(o[2 * ct + 1], p16[kt], v[2], v[3]);
            }
            mma16(lacc, p16[kt], ONES, ONES);
        }
    }

    // Epilogue: direct per-warp write (warp owns complete rows), no smem exchange
    float* ob = out + (size_t)b * CDIM * NPIX + r0 + warp * 16;
    const float il0 = 1.0f / lacc[0];
    const float il8 = 1.0f / lacc[2];
    const int nlo = g, nhi = g + 8;
#pragma unroll
    for (int nf = 0; nf < 8; nf++) {
        const int c0 = nf * 8 + 2 * t;
        ob[(size_t)c0 * NPIX + nlo]       = o[nf][0] * il0;
        ob[(size_t)(c0 + 1) * NPIX + nlo] = o[nf][1] * il0;
        ob[(size_t)c0 * NPIX + nhi]       = o[nf][2] * il8;
        ob[(size_t)(c0 + 1) * NPIX + nhi] = o[nf][3] * il8;
    }
}

// ---------------------------------------------------------------------------
extern "C" void kernel_launch(void* const* d_in, const int* in_sizes, int n_in,
                              void* d_out, int out_size)
{
    const float* query  = (const float*)d_in[0];
    const float* keys   = (const float*)d_in[1];
    const float* values = (const float*)d_in[2];
    const float* Wq     = (const float*)d_in[3];
    const float* bq     = (const float*)d_in[4];
    float* out = (float*)d_out;

    static bool attr_set = false;
    if (!attr_set) {
        cudaFuncSetAttribute(attn_kernel, cudaFuncAttributeMaxDynamicSharedMemorySize, SMEM_BYTES);
        attr_set = true;
    }
    cvt_kernel<<<BATCH * CDIM * NPIX / 4096, 256>>>(keys, values);
    qproj_kernel<<<dim3(100, BATCH), 256>>>(query, Wq, bq);
    attn_kernel<<<dim3(NPIX / QT, BATCH), 128, SMEM_BYTES>>>(out);
}

// round 15
// speedup vs baseline: 1.1713x; 1.1713x over previous
#include <cuda_runtime.h>
#include <cuda_fp16.h>
#include <cstdint>
#include <math.h>

#define BATCH 4
#define CDIM  64
#define NPIX  6400
#define QT    64
#define NCHUNK 50   // 128 KV cols per chunk, 2 subtiles of 64

__device__ __half g_k[BATCH * CDIM * NPIX];   // fp16 keys,   [b][c][m]
__device__ __half g_v[BATCH * CDIM * NPIX];   // fp16 values, [b][c][m]

// ---------------- helpers ----------------
__device__ __forceinline__ uint32_t smem_u32(const void* p) {
    uint32_t a;
    asm("{ .reg .u64 t; cvta.to.shared.u64 t, %1; cvt.u32.u64 %0, t; }" : "=r"(a) : "l"(p));
    return a;
}
__device__ __forceinline__ uint32_t pkhf(float hi, float lo) {
    uint32_t d; asm("cvt.rn.f16x2.f32 %0, %1, %2;" : "=r"(d) : "f"(hi), "f"(lo));
    return d;
}
__device__ __forceinline__ uint32_t ex2h2(uint32_t x) {
    uint32_t d; asm("ex2.approx.f16x2 %0, %1;" : "=r"(d) : "r"(x));
    return d;
}
__device__ __forceinline__ void cp16(uint32_t dst, const void* src) {
    asm volatile("cp.async.cg.shared.global [%0], [%1], 16;" :: "r"(dst), "l"(src) : "memory");
}
#define CP_COMMIT() asm volatile("cp.async.commit_group;" ::: "memory")
#define CP_WAIT0()  asm volatile("cp.async.wait_group 0;"  ::: "memory")

__device__ __forceinline__ void ldsm4(uint32_t* r, uint32_t a) {
    asm volatile("ldmatrix.sync.aligned.m8n8.x4.shared.b16 {%0,%1,%2,%3}, [%4];"
                 : "=r"(r[0]), "=r"(r[1]), "=r"(r[2]), "=r"(r[3]) : "r"(a));
}
__device__ __forceinline__ void ldsm4t(uint32_t* r, uint32_t a) {
    asm volatile("ldmatrix.sync.aligned.m8n8.x4.trans.shared.b16 {%0,%1,%2,%3}, [%4];"
                 : "=r"(r[0]), "=r"(r[1]), "=r"(r[2]), "=r"(r[3]) : "r"(a));
}
__device__ __forceinline__ void mma16(float* c, const uint32_t* a, uint32_t b0, uint32_t b1) {
    asm volatile("mma.sync.aligned.m16n8k16.row.col.f32.f16.f16.f32 "
                 "{%0,%1,%2,%3},{%4,%5,%6,%7},{%8,%9},{%0,%1,%2,%3};"
                 : "+f"(c[0]), "+f"(c[1]), "+f"(c[2]), "+f"(c[3])
                 : "r"(a[0]), "r"(a[1]), "r"(a[2]), "r"(a[3]), "r"(b0), "r"(b1));
}

// smem: per buffer one 128-col chunk = two 64-col subtiles of [64][72] half
#define TILE_B  9216u
#define CHUNK_B (2u * TILE_B)              // 18432
#define SMEM_BYTES (4u * CHUNK_B)          // 73728: K[2 bufs], V[2 bufs]
// prologue overlay: qsm/wsm live in the vsb[1] region (overwritten by chunk 1)
#define QSM_OFF (3u * CHUNK_B)             // 55296: query^T [64 n][72 d] half
#define WSM_OFF (3u * CHUNK_B + TILE_B)    // 64512: Wq      [64 c][72 d] half

// ---------------- Kernel 0: fp32 -> fp16 conversion, 4x float4 per thread ------
__global__ void cvt_kernel(const float* __restrict__ keys, const float* __restrict__ values)
{
    const int base = blockIdx.x * 1024 + threadIdx.x;
#pragma unroll
    for (int j = 0; j < 4; j++) {
        const int idx = base + j * 256;
        const float4 kv = ((const float4*)keys)[idx];
        const float4 vv = ((const float4*)values)[idx];
        uint2 ko, vo;
        ko.x = pkhf(kv.y, kv.x); ko.y = pkhf(kv.w, kv.z);
        vo.x = pkhf(vv.y, vv.x); vo.y = pkhf(vv.w, vv.z);
        ((uint2*)g_k)[idx] = ko;
        ((uint2*)g_v)[idx] = vo;
    }
}

// ---------------- KV fp16 chunk loader (128 cols) via cp.async, 128 threads ----
__device__ __forceinline__ void load_kv(uint32_t ksb, uint32_t vsb,
                                        const __half* kb, const __half* vb,
                                        int m0, int tid)
{
#pragma unroll
    for (int i = 0; i < 8; i++) {
        int idx = tid + (i << 7);          // 0..1023
        int c = idx >> 4, m = (idx & 15) << 3;   // m in 0..120 step 8
        uint32_t sub = (m & 64) ? TILE_B : 0u;
        uint32_t soff = sub + (uint32_t)(c * 72 + (m & 63)) * 2u;
        cp16(ksb + soff, kb + (size_t)c * NPIX + m0 + m);
        cp16(vsb + soff, vb + (size_t)c * NPIX + m0 + m);
    }
    CP_COMMIT();
}

// ---------------- Kernel 1: fused attention (in-CTA q projection) --------------
// 128 threads = 4 warps. warp = wrow + 2*nhalf (wrow = q-row half, nhalf =
// KV-column half). Prologue: project q on tensor cores from smem-staged fp16
// query^T / Wq; C-frags + bias, scaled, pack straight into qa A-frags.
__global__ void __launch_bounds__(128, 3)
attn_kernel(const float* __restrict__ query,
            const float* __restrict__ Wq,
            const float* __restrict__ bq,
            float* __restrict__ out)
{
    extern __shared__ uint32_t smu[];
    const uint32_t sbase = smem_u32(smu);
    const int tid  = threadIdx.x;
    const int lane = tid & 31, warp = tid >> 5;
    const int wrow = warp & 1, nhalf = warp >> 1;
    const int g = lane >> 2, t = lane & 3;
    const int b  = blockIdx.y;
    const int r0 = blockIdx.x * QT;

    const uint32_t ksb[2] = {sbase, sbase + CHUNK_B};
    const uint32_t vsb[2] = {sbase + 2u * CHUNK_B, sbase + 3u * CHUNK_B};
    const uint32_t mbase = (uint32_t)(nhalf * 32);
    const uint32_t ONES = 0x3C003C00u;

    // ---- prologue: stage query^T and Wq as fp16 into the vsb[1] region ----
    {
        __half* qsm = (__half*)((char*)smu + QSM_OFF);
        __half* wsm = (__half*)((char*)smu + WSM_OFF);
        const float* qg = query + (size_t)b * CDIM * NPIX + r0;
#pragma unroll
        for (int i = 0; i < 8; i++) {
            int idx = tid + (i << 7);              // 0..1023
            int d = idx >> 4, n4 = (idx & 15) << 2;
            float4 qv = *(const float4*)(qg + (size_t)d * NPIX + n4);
            qsm[(n4 + 0) * 72 + d] = __float2half_rn(qv.x);
            qsm[(n4 + 1) * 72 + d] = __float2half_rn(qv.y);
            qsm[(n4 + 2) * 72 + d] = __float2half_rn(qv.z);
            qsm[(n4 + 3) * 72 + d] = __float2half_rn(qv.w);
            int c = idx >> 4, d4 = (idx & 15) << 2;
            float4 wv = *(const float4*)(Wq + (size_t)c * CDIM + d4);
            *(uint32_t*)&wsm[c * 72 + d4]     = pkhf(wv.y, wv.x);
            *(uint32_t*)&wsm[c * 72 + d4 + 2] = pkhf(wv.w, wv.z);
        }
    }
    __syncthreads();

    const __half* kb = g_k + (size_t)b * CDIM * NPIX;
    const __half* vb = g_v + (size_t)b * CDIM * NPIX;
    load_kv(ksb[0], vsb[0], kb, vb, 0, tid);   // chunk 0 overlaps qproj MMAs

    // ---- in-warp q projection: qc[n][c] = sum_d q[n][d] * Wq[c][d] ----
    uint32_t qa[2][4][4];
    {
        const float scale = 0.125f * 1.4426950408889634f;  // 64^-0.5 * log2(e)
        float qc[2][8][4] = {};
        // A-frag address (m16k16): row = wrow*32 + h*16 + (lane&7) + ((lane>>3)&1)*8,
        // k-chunk = (lane>>4)*8
        const uint32_t arow = (uint32_t)(wrow * 32 + (lane & 7) + (((lane >> 3) & 1) << 3));
        const uint32_t acol = (uint32_t)((lane >> 4) << 3);
        // B-frag address (V-style): row = ct*16 + (lane&7) + ((lane>>4)<<3),
        // col = ks*16 + (((lane>>3)&1)<<3)
        const uint32_t brow = (uint32_t)((lane & 7) + ((lane >> 4) << 3));
        const uint32_t bcol = (uint32_t)(((lane >> 3) & 1) << 3);
#pragma unroll
        for (int ks = 0; ks < 4; ks++) {
            uint32_t a0[4], a1[4];
            ldsm4(a0, sbase + QSM_OFF + ((arow)      * 72u + (uint32_t)(ks * 16) + acol) * 2u);
            ldsm4(a1, sbase + QSM_OFF + ((arow + 16) * 72u + (uint32_t)(ks * 16) + acol) * 2u);
#pragma unroll
            for (int ct = 0; ct < 4; ct++) {
                uint32_t w[4];
                ldsm4(w, sbase + WSM_OFF
                         + ((uint32_t)(ct * 16) + brow) * 144u
                         + ((uint32_t)(ks * 16) + bcol) * 2u);
                mma16(qc[0][2 * ct],     a0, w[0], w[1]);
                mma16(qc[0][2 * ct + 1], a0, w[2], w[3]);
                mma16(qc[1][2 * ct],     a1, w[0], w[1]);
                mma16(qc[1][2 * ct + 1], a1, w[2], w[3]);
            }
        }
        // bias + scale, pack into fp16 A-frags (same identity as P packing)
#pragma unroll
        for (int ks = 0; ks < 4; ks++) {
            const float b0a = bq[(2 * ks) * 8 + 2 * t],     b1a = bq[(2 * ks) * 8 + 2 * t + 1];
            const float b0b = bq[(2 * ks + 1) * 8 + 2 * t], b1b = bq[(2 * ks + 1) * 8 + 2 * t + 1];
#pragma unroll
            for (int h = 0; h < 2; h++) {
                qa[h][ks][0] = pkhf((qc[h][2 * ks][1] + b1a) * scale,
                                    (qc[h][2 * ks][0] + b0a) * scale);
                qa[h][ks][1] = pkhf((qc[h][2 * ks][3] + b1a) * scale,
                                    (qc[h][2 * ks][2] + b0a) * scale);
                qa[h][ks][2] = pkhf((qc[h][2 * ks + 1][1] + b1b) * scale,
                                    (qc[h][2 * ks + 1][0] + b0b) * scale);
                qa[h][ks][3] = pkhf((qc[h][2 * ks + 1][3] + b1b) * scale,
                                    (qc[h][2 * ks + 1][2] + b0b) * scale);
            }
        }
    }
    CP_WAIT0();          // chunk 0 landed
    __syncthreads();     // all warps done reading qsm/wsm (chunk 1 overwrites)

    // LDSM lane-address bases (halves -> bytes x2)
    const uint32_t kaddr0 = ((uint32_t)((lane & 15) * 72) + mbase + (uint32_t)((lane >> 4) << 3)) * 2u;
    const uint32_t vaddr0 = ((uint32_t)(((lane & 7) + ((lane >> 4) << 3)) * 72)
                             + mbase + (uint32_t)(((lane >> 3) & 1) << 3)) * 2u;

    float o[2][8][4] = {};
    float lacc[2][4] = {};

    for (int it = 0; it < NCHUNK; it++) {
        const int cur = it & 1;
        if (it + 1 < NCHUNK)
            load_kv(ksb[cur ^ 1], vsb[cur ^ 1], kb, vb, (it + 1) * 128, tid);

#pragma unroll
        for (int sub = 0; sub < 2; sub++) {
            const uint32_t kbb = ksb[cur] + (uint32_t)sub * TILE_B;
            const uint32_t vbb = vsb[cur] + (uint32_t)sub * TILE_B;

            // GEMM1 (fp16): S[32 x 32] = Q K^T over warp's m-half
            float s[2][4][4] = {};
#pragma unroll
            for (int ks = 0; ks < 4; ks++)
#pragma unroll
                for (int nt = 0; nt < 2; nt++) {
                    uint32_t r[4];
                    ldsm4t(r, kbb + kaddr0 + (uint32_t)(ks * 16 * 72 + nt * 16) * 2u);
                    mma16(s[0][2 * nt],     qa[0][ks], r[0], r[1]);
                    mma16(s[1][2 * nt],     qa[1][ks], r[0], r[1]);
                    mma16(s[0][2 * nt + 1], qa[0][ks], r[2], r[3]);
                    mma16(s[1][2 * nt + 1], qa[1][ks], r[2], r[3]);
                }

            // Softmax (no max): pack S pairs -> fp16, packed exp2; P = A-frags
            uint32_t p16[2][2][4];
#pragma unroll
            for (int kt = 0; kt < 2; kt++)
#pragma unroll
                for (int h = 0; h < 2; h++) {
                    p16[kt][h][0] = ex2h2(pkhf(s[h][2 * kt][1],     s[h][2 * kt][0]));
                    p16[kt][h][1] = ex2h2(pkhf(s[h][2 * kt][3],     s[h][2 * kt][2]));
                    p16[kt][h][2] = ex2h2(pkhf(s[h][2 * kt + 1][1], s[h][2 * kt + 1][0]));
                    p16[kt][h][3] = ex2h2(pkhf(s[h][2 * kt + 1][3], s[h][2 * kt + 1][2]));
                }
            // l row-sums via ones-MMA (exact fp32, consistent with GEMM2's P)
            mma16(lacc[0], p16[0][0], ONES, ONES);
            mma16(lacc[1], p16[0][1], ONES, ONES);
            mma16(lacc[0], p16[1][0], ONES, ONES);
            mma16(lacc[1], p16[1][1], ONES, ONES);

            // GEMM2 (fp16): O += P V
#pragma unroll
            for (int kt = 0; kt < 2; kt++)
#pragma unroll
                for (int ct = 0; ct < 4; ct++) {
                    uint32_t v[4];
                    ldsm4(v, vbb + vaddr0 + (uint32_t)(ct * 16 * 72 + kt * 16) * 2u);
                    mma16(o[0][2 * ct],     p16[kt][0], v[0], v[1]);
                    mma16(o[1][2 * ct],     p16[kt][1], v[0], v[1]);
                    mma16(o[0][2 * ct + 1], p16[kt][0], v[2], v[3]);
                    mma16(o[1][2 * ct + 1], p16[kt][1], v[2], v[3]);
                }
        }

        CP_WAIT0();
        __syncthreads();
    }

    // Epilogue: combine column-half partials through smem, then scaled STG.
    float* obuf = (float*)smu;            // [64][65]
    float* lbuf = obuf + 64 * 65;         // [64]
    if (nhalf == 0) {
#pragma unroll
        for (int h = 0; h < 2; h++) {
            const int row0 = wrow * 32 + h * 16 + g, row8 = row0 + 8;
#pragma unroll
            for (int nf = 0; nf < 8; nf++) {
                const int c0 = nf * 8 + 2 * t;
                obuf[row0 * 65 + c0]     = o[h][nf][0];
                obuf[row0 * 65 + c0 + 1] = o[h][nf][1];
                obuf[row8 * 65 + c0]     = o[h][nf][2];
                obuf[row8 * 65 + c0 + 1] = o[h][nf][3];
            }
            if (t == 0) { lbuf[row0] = lacc[h][0]; lbuf[row8] = lacc[h][2]; }
        }
    }
    __syncthreads();
    if (nhalf == 1) {
        float* ob = out + (size_t)b * CDIM * NPIX + r0 + wrow * 32;
#pragma unroll
        for (int h = 0; h < 2; h++) {
            const int row0 = wrow * 32 + h * 16 + g, row8 = row0 + 8;
            const float il0 = 1.0f / (lacc[h][0] + lbuf[row0]);
            const float il8 = 1.0f / (lacc[h][2] + lbuf[row8]);
            const int nlo = h * 16 + g, nhi = nlo + 8;
#pragma unroll
            for (int nf = 0; nf < 8; nf++) {
                const int c0 = nf * 8 + 2 * t;
                ob[(size_t)c0 * NPIX + nlo]       = (o[h][nf][0] + obuf[row0 * 65 + c0])     * il0;
                ob[(size_t)(c0 + 1) * NPIX + nlo] = (o[h][nf][1] + obuf[row0 * 65 + c0 + 1]) * il0;
                ob[(size_t)c0 * NPIX + nhi]       = (o[h][nf][2] + obuf[row8 * 65 + c0])     * il8;
                ob[(size_t)(c0 + 1) * NPIX + nhi] = (o[h][nf][3] + obuf[row8 * 65 + c0 + 1]) * il8;
            }
        }
    }
}

// ---------------------------------------------------------------------------
extern "C" void kernel_launch(void* const* d_in, const int* in_sizes, int n_in,
                              void* d_out, int out_size)
{
    const float* query  = (const float*)d_in[0];
    const float* keys   = (const float*)d_in[1];
    const float* values = (const float*)d_in[2];
    const float* Wq     = (const float*)d_in[3];
    const float* bq     = (const float*)d_in[4];
    float* out = (float*)d_out;

    static bool attr_set = false;
    if (!attr_set) {
        cudaFuncSetAttribute(attn_kernel, cudaFuncAttributeMaxDynamicSharedMemorySize, SMEM_BYTES);
        attr_set = true;
    }
    cvt_kernel<<<BATCH * CDIM * NPIX / 4096, 256>>>(keys, values);
    attn_kernel<<<dim3(NPIX / QT, BATCH), 128, SMEM_BYTES>>>(query, Wq, bq, out);
}